// round 6
// baseline (speedup 1.0000x reference)
#include <cuda_runtime.h>
#include <cuda_bf16.h>

// Local Moran's I:
//   xbar = mean(X)
//   xn_ij = X[ids[i][j]] - xbar
//   S_i   = sum_j w_ij * xn_ij^2
//   lag_i = sum_j w_ij * xn_ij
//   out_i = (X[i]-xbar) * lag_i * (K-1) / S_i
//
// N = 1,000,000, K = 32.
//
// Bottleneck model: 32M random 4B gathers into the 4MB X table.
//  - keep X resident in L2 by streaming W/IDS with evict-first (__ldcs)
//  - maximize per-warp MLP: batch all id loads, then all 32 gathers.

#define KNBR 32
#define NUM_PARTIAL_BLOCKS 1024

__device__ float g_partials[NUM_PARTIAL_BLOCKS];
__device__ float g_mean;

// ---------------- Stage 1: per-block partial sums (deterministic order) ----
// N = 1e6 = 250000 float4. 1024 blocks x 256 threads, grid-stride on float4.
__global__ __launch_bounds__(256) void moran_sum_kernel(
    const float4* __restrict__ X4, int n4) {
    __shared__ float sh[256];
    float s = 0.0f;
    for (int i = blockIdx.x * blockDim.x + threadIdx.x; i < n4;
         i += gridDim.x * blockDim.x) {
        float4 v = X4[i];
        s += (v.x + v.y) + (v.z + v.w);
    }
    sh[threadIdx.x] = s;
    __syncthreads();
#pragma unroll
    for (int off = 128; off > 0; off >>= 1) {
        if (threadIdx.x < off) sh[threadIdx.x] += sh[threadIdx.x + off];
        __syncthreads();
    }
    if (threadIdx.x == 0) g_partials[blockIdx.x] = sh[0];
}

// ---------------- Stage 2: reduce partials -> mean --------------------------
__global__ void moran_finalize_mean_kernel(int n) {
    __shared__ float sh[NUM_PARTIAL_BLOCKS];
    sh[threadIdx.x] = g_partials[threadIdx.x];
    __syncthreads();
#pragma unroll
    for (int off = NUM_PARTIAL_BLOCKS / 2; off > 0; off >>= 1) {
        if (threadIdx.x < off) sh[threadIdx.x] += sh[threadIdx.x + off];
        __syncthreads();
    }
    if (threadIdx.x == 0) g_mean = sh[0] / (float)n;
}

// ---------------- Stage 3: main Local Moran kernel --------------------------
__global__ __launch_bounds__(256) void moran_main_kernel(
    const float* __restrict__ X,
    const float4* __restrict__ W,    // [N, 8] float4 view of [N, 32]
    const int4* __restrict__ IDS,    // [N, 8] int4 view of [N, 32]
    float* __restrict__ out, int n) {
    int i = blockIdx.x * blockDim.x + threadIdx.x;
    if (i >= n) return;

    const float mean = g_mean;
    const float4* wrow = W + (size_t)i * (KNBR / 4);
    const int4* idrow = IDS + (size_t)i * (KNBR / 4);

    // 1) Front-batch all index loads (streaming: do not pollute L2, X must
    //    stay resident there).
    int4 id[KNBR / 4];
#pragma unroll
    for (int j = 0; j < KNBR / 4; j++) id[j] = __ldcs(idrow + j);

    // 2) Fire all 32 gathers back-to-back: MLP ~= 32 per warp, covers the
    //    ~234-262 cyc L2 hit latency.
    float xs[KNBR];
#pragma unroll
    for (int j = 0; j < KNBR / 4; j++) {
        xs[4 * j + 0] = __ldg(X + id[j].x);
        xs[4 * j + 1] = __ldg(X + id[j].y);
        xs[4 * j + 2] = __ldg(X + id[j].z);
        xs[4 * j + 3] = __ldg(X + id[j].w);
    }

    // 3) Stream the weights (evict-first) and accumulate.
    float lag = 0.0f;
    float S = 0.0f;
#pragma unroll
    for (int j = 0; j < KNBR / 4; j++) {
        float4 w = __ldcs(wrow + j);
        float x0 = xs[4 * j + 0] - mean;
        float x1 = xs[4 * j + 1] - mean;
        float x2 = xs[4 * j + 2] - mean;
        float x3 = xs[4 * j + 3] - mean;

        float t0 = w.x * x0;
        float t1 = w.y * x1;
        float t2 = w.z * x2;
        float t3 = w.w * x3;

        lag += (t0 + t1) + (t2 + t3);
        S = fmaf(t0, x0, S);
        S = fmaf(t1, x1, S);
        S = fmaf(t2, x2, S);
        S = fmaf(t3, x3, S);
    }

    float xa = __ldg(X + i) - mean;
    out[i] = xa * lag * (float)(KNBR - 1) / S;
}

extern "C" void kernel_launch(void* const* d_in, const int* in_sizes, int n_in,
                              void* d_out, int out_size) {
    const float* X = (const float*)d_in[0];
    const float* W = (const float*)d_in[1];
    const int* IDS = (const int*)d_in[2];
    float* out = (float*)d_out;
    int n = in_sizes[0];

    // Stage 1+2: deterministic mean
    moran_sum_kernel<<<NUM_PARTIAL_BLOCKS, 256>>>((const float4*)X, n / 4);
    moran_finalize_mean_kernel<<<1, NUM_PARTIAL_BLOCKS>>>(n);

    // Stage 3: main kernel
    int threads = 256;
    int blocks = (n + threads - 1) / threads;
    moran_main_kernel<<<blocks, threads>>>(
        X, (const float4*)W, (const int4*)IDS, out, n);
}

// round 7
// speedup vs baseline: 1.3662x; 1.3662x over previous
#include <cuda_runtime.h>
#include <cuda_bf16.h>

// Local Moran's I:
//   xbar = mean(X)
//   xn_ij = X[ids[i][j]] - xbar
//   S_i   = sum_j w_ij * xn_ij^2
//   lag_i = sum_j w_ij * xn_ij
//   out_i = (X[i]-xbar) * lag_i * (K-1) / S_i
//
// N = 1,000,000, K = 32.
//
// Bottleneck model (validated R4/R6): L1tex WAVEFRONTS, not bytes.
// Thread-per-row made every streaming LDG touch 32 lines (stride-128B) ->
// ~32 wavefronts/instr. This version uses 4 rows per warp / 8 lanes per row
// so every W/IDS load instruction is 512B-contiguous (4 wf covering 4 rows),
// leaving only the irreducible random-gather wavefronts (~30/row).

#define KNBR 32
#define NUM_PARTIAL_BLOCKS 1024

__device__ float g_partials[NUM_PARTIAL_BLOCKS];
__device__ float g_mean;

// ---------------- Stage 1: per-block partial sums (deterministic order) ----
__global__ __launch_bounds__(256) void moran_sum_kernel(
    const float4* __restrict__ X4, int n4) {
    __shared__ float sh[256];
    float s = 0.0f;
    for (int i = blockIdx.x * blockDim.x + threadIdx.x; i < n4;
         i += gridDim.x * blockDim.x) {
        float4 v = X4[i];
        s += (v.x + v.y) + (v.z + v.w);
    }
    sh[threadIdx.x] = s;
    __syncthreads();
#pragma unroll
    for (int off = 128; off > 0; off >>= 1) {
        if (threadIdx.x < off) sh[threadIdx.x] += sh[threadIdx.x + off];
        __syncthreads();
    }
    if (threadIdx.x == 0) g_partials[blockIdx.x] = sh[0];
}

// ---------------- Stage 2: reduce partials -> mean --------------------------
__global__ void moran_finalize_mean_kernel(int n) {
    __shared__ float sh[NUM_PARTIAL_BLOCKS];
    sh[threadIdx.x] = g_partials[threadIdx.x];
    __syncthreads();
#pragma unroll
    for (int off = NUM_PARTIAL_BLOCKS / 2; off > 0; off >>= 1) {
        if (threadIdx.x < off) sh[threadIdx.x] += sh[threadIdx.x + off];
        __syncthreads();
    }
    if (threadIdx.x == 0) g_mean = sh[0] / (float)n;
}

// ---------------- Stage 3: main Local Moran kernel --------------------------
// 4 rows per warp, 8 lanes per row. Lane l: row_local = l>>3, seg = l&7.
// Each lane handles one float4/int4 of its row (32 floats per row = 8 segs).
__global__ __launch_bounds__(256) void moran_main_kernel(
    const float* __restrict__ X,
    const float4* __restrict__ W,    // float4 view of [N, 32]
    const int4* __restrict__ IDS,    // int4 view of [N, 32]
    float* __restrict__ out, int n) {
    int warp_global = (blockIdx.x * blockDim.x + threadIdx.x) >> 5;
    int lane = threadIdx.x & 31;
    int row = warp_global * 4 + (lane >> 3);
    int seg = lane & 7;
    if (row >= n) return;

    const float mean = g_mean;
    size_t idx4 = (size_t)row * (KNBR / 4) + seg;

    // Coalesced: the warp's 32 lanes cover a contiguous 512B range.
    float4 w = __ldcs(W + idx4);
    int4 id = __ldcs(IDS + idx4);

    // 4 random gathers per lane (irreducible wavefront cost).
    float x0 = __ldg(X + id.x) - mean;
    float x1 = __ldg(X + id.y) - mean;
    float x2 = __ldg(X + id.z) - mean;
    float x3 = __ldg(X + id.w) - mean;

    float t0 = w.x * x0;
    float t1 = w.y * x1;
    float t2 = w.z * x2;
    float t3 = w.w * x3;

    float lag = (t0 + t1) + (t2 + t3);
    float S = fmaf(t0, x0, fmaf(t1, x1, fmaf(t2, x2, t3 * x3)));

    // Reduce across the 8 lanes sharing this row (offsets 4,2,1 stay in-group).
#pragma unroll
    for (int off = 4; off > 0; off >>= 1) {
        lag += __shfl_xor_sync(0xFFFFFFFFu, lag, off);
        S += __shfl_xor_sync(0xFFFFFFFFu, S, off);
    }

    if (seg == 0) {
        float xa = __ldg(X + row) - mean;
        out[row] = xa * lag * (float)(KNBR - 1) / S;
    }
}

extern "C" void kernel_launch(void* const* d_in, const int* in_sizes, int n_in,
                              void* d_out, int out_size) {
    const float* X = (const float*)d_in[0];
    const float* W = (const float*)d_in[1];
    const int* IDS = (const int*)d_in[2];
    float* out = (float*)d_out;
    int n = in_sizes[0];

    // Stage 1+2: deterministic mean
    moran_sum_kernel<<<NUM_PARTIAL_BLOCKS, 256>>>((const float4*)X, n / 4);
    moran_finalize_mean_kernel<<<1, NUM_PARTIAL_BLOCKS>>>(n);

    // Stage 3: 4 rows per warp -> 32 rows per 256-thread block.
    int threads = 256;
    int rows_per_block = (threads / 32) * 4;  // 32
    int blocks = (n + rows_per_block - 1) / rows_per_block;
    moran_main_kernel<<<blocks, threads>>>(
        X, (const float4*)W, (const int4*)IDS, out, n);
}